// round 17
// baseline (speedup 1.0000x reference)
#include <cuda_runtime.h>
#include <cuda_bf16.h>
#include <cuda_fp16.h>
#include <cstdint>

#define NTOK 4096
#define CCH 512
#define NH 8
#define HD 64
#define MQKV 1536

// Scratch (device globals; no runtime allocation allowed)
__device__ float g_qkv[MQKV * NTOK];        // rows 0..511 q*scale (fp32)
__device__ uint32_t g_v3[NH * 64 * 2560];   // V fp16x2 smem-image: [h][tile][2560w]
__device__ uint32_t g_k2[NH * 4096 * 32];   // K bf16x2 frag order (proven)
__device__ uint32_t g_xt[4096 * 256];       // x^T fp16x2, [n][kword perm]
__device__ uint32_t g_att_t[4096 * 256];    // att^T fp16x2, [tok][cword perm]
__device__ uint32_t g_wqkv_h[MQKV * 256];   // w_qkv fp16x2 [m][kword natural]
__device__ uint32_t g_wout_h[CCH * 256];    // w_out fp16x2 [m][kword natural]

__device__ __forceinline__ uint32_t pack_bf16x2(float lo, float hi) {
    uint32_t r;
    asm("cvt.rn.bf16x2.f32 %0, %1, %2;" : "=r"(r) : "f"(hi), "f"(lo));
    return r;
}
__device__ __forceinline__ uint32_t pack_f16x2(float lo, float hi) {
    uint32_t r;
    asm("cvt.rn.f16x2.f32 %0, %1, %2;" : "=r"(r) : "f"(hi), "f"(lo));
    return r;
}
__device__ __forceinline__ uint32_t ex2_f16x2(uint32_t x) {
    uint32_t y;
    asm("ex2.approx.f16x2 %0, %1;" : "=r"(y) : "r"(x));
    return y;
}
__device__ __forceinline__ void mma_f16(float c[4], const uint32_t a[4],
                                        uint32_t b0, uint32_t b1) {
    asm volatile(
        "mma.sync.aligned.m16n8k16.row.col.f32.f16.f16.f32 "
        "{%0,%1,%2,%3}, {%4,%5,%6,%7}, {%8,%9}, {%0,%1,%2,%3};"
        : "+f"(c[0]), "+f"(c[1]), "+f"(c[2]), "+f"(c[3])
        : "r"(a[0]), "r"(a[1]), "r"(a[2]), "r"(a[3]), "r"(b0), "r"(b1));
}
__device__ __forceinline__ void mma_bf16(float c[4], const uint32_t a[4],
                                         uint32_t b0, uint32_t b1) {
    asm volatile(
        "mma.sync.aligned.m16n8k16.row.col.f32.bf16.bf16.f32 "
        "{%0,%1,%2,%3}, {%4,%5,%6,%7}, {%8,%9}, {%0,%1,%2,%3};"
        : "+f"(c[0]), "+f"(c[1]), "+f"(c[2]), "+f"(c[3])
        : "r"(a[0]), "r"(a[1]), "r"(a[2]), "r"(a[3]), "r"(b0), "r"(b1));
}
__device__ __forceinline__ uint32_t smem_u32(const void* p) {
    uint32_t a;
    asm("{ .reg .u64 t; cvta.to.shared.u64 t, %1; cvt.u32.u64 %0, t; }"
        : "=r"(a) : "l"(p));
    return a;
}
__device__ __forceinline__ void cp16(uint32_t dst, const void* src) {
    asm volatile("cp.async.ca.shared.global [%0], [%1], 16;" :: "r"(dst), "l"(src));
}
// fragment word permutation within an 8-kpair chunk (proven in g_k2)
__device__ __forceinline__ int kpos(int d) {
    int dp = d >> 1, dpl = dp & 7, kc = dp >> 3;
    return kc * 16 + ((dpl & 3) * 2 + (dpl >> 2)) * 2 + (d & 1);
}

// ---------------------------------------------------------------------------
// Pre-pass 1: convert w_qkv, w_out to fp16 word arrays (natural [m][k]).
// ---------------------------------------------------------------------------
__global__ __launch_bounds__(256) void conv_w(const float* __restrict__ wqkv,
                                              const float* __restrict__ wout) {
    int i = blockIdx.x * 256 + threadIdx.x;
    if (i < 393216) {
        float2 v = ((const float2*)wqkv)[i];
        g_wqkv_h[i] = pack_f16x2(v.x, v.y);
    } else {
        float2 v = ((const float2*)wout)[i - 393216];
        g_wout_h[i - 393216] = pack_f16x2(v.x, v.y);
    }
}

// ---------------------------------------------------------------------------
// Pre-pass 2: transpose x -> g_xt [n][256 kwords] fp16 with frag word perm.
// ---------------------------------------------------------------------------
__global__ __launch_bounds__(256) void trans_x(const float* __restrict__ x) {
    __shared__ float tile[64][65];
    const int bn = blockIdx.x, bk = blockIdx.y;
    const int t = threadIdx.x;
    const int tn = t & 63, tk4 = t >> 6;
#pragma unroll
    for (int r = 0; r < 16; r++) {
        int k = tk4 * 16 + r;
        tile[k][tn] = x[(bk * 64 + k) * 4096 + bn * 64 + tn];
    }
    __syncthreads();
    const int n = t >> 2, wq = t & 3;
    uint32_t* dst = g_xt + (bn * 64 + n) * 256 + bk * 32 + wq * 8;
#pragma unroll
    for (int i = 0; i < 8; i++) {
        int wrd = wq * 8 + i;
        int wc = wrd & 7;
        int p = (wc & 1) ? (4 + (wc >> 1)) : (wc >> 1);
        int k0 = (wrd >> 3) * 16 + 2 * p;
        dst[i] = pack_f16x2(tile[k0][n], tile[k0 + 1][n]);
    }
}

// ---------------------------------------------------------------------------
// fp16 tensor-core GEMM (proven round-15 structure).
// flags bit0 = qkv mode (Q->g_qkv, K->g_k2, V->g_v3 image), else out-proj.
// ---------------------------------------------------------------------------
#define ASTR2 36
#define BSTR2 40
#define AFLW (128 * ASTR2)
#define BFLW (128 * BSTR2)

__global__ __launch_bounds__(256, 2) void gemm_f16(float* __restrict__ Cg,
                                                   const float* __restrict__ bias,
                                                   const float* __restrict__ res,
                                                   int flags) {
    extern __shared__ uint32_t smw[];
    const uint32_t sb = smem_u32(smw);

    const uint32_t* A = (flags & 1) ? g_wqkv_h : g_wout_h;
    const uint32_t* B = (flags & 1) ? g_xt : g_att_t;

    const int t = threadIdx.x, lane = t & 31, w = t >> 5;
    const int g = lane >> 2, q4 = lane & 3;
    const int mw = (w >> 1) * 32;
    const int nw = (w & 1) * 64;
    const int m0 = blockIdx.y * 128, n0 = blockIdx.x * 128;

    float c[2][8][4] = {};

    int row4[4], cof4[4];
#pragma unroll
    for (int r = 0; r < 4; r++) {
        int cid = t + 256 * r;
        row4[r] = cid >> 3;  cof4[r] = (cid & 7) * 4;
    }

#pragma unroll
    for (int r = 0; r < 4; r++)
        cp16(sb + (row4[r] * ASTR2 + cof4[r]) * 4,
             &A[(m0 + row4[r]) * 256 + cof4[r]]);
#pragma unroll
    for (int r = 0; r < 4; r++)
        cp16(sb + 36864 + (row4[r] * BSTR2 + cof4[r]) * 4,
             &B[(n0 + row4[r]) * 256 + cof4[r]]);
    asm volatile("cp.async.commit_group;" ::: "memory");

    for (int s = 0; s < 8; s++) {
        const int cur = s & 1;
        asm volatile("cp.async.wait_group 0;" ::: "memory");
        __syncthreads();

        if (s < 7) {
            const int w0 = (s + 1) * 32;
            const uint32_t ad = sb + ((cur ^ 1) ? 18432u : 0u);
            const uint32_t bd = sb + 36864 + ((cur ^ 1) ? 20480u : 0u);
#pragma unroll
            for (int r = 0; r < 4; r++)
                cp16(ad + (row4[r] * ASTR2 + cof4[r]) * 4,
                     &A[(m0 + row4[r]) * 256 + w0 + cof4[r]]);
#pragma unroll
            for (int r = 0; r < 4; r++)
                cp16(bd + (row4[r] * BSTR2 + cof4[r]) * 4,
                     &B[(n0 + row4[r]) * 256 + w0 + cof4[r]]);
            asm volatile("cp.async.commit_group;" ::: "memory");
        }

        const uint32_t* As = smw + cur * AFLW;
        const uint32_t* Bs = smw + 2 * AFLW + cur * BFLW;
#pragma unroll
        for (int kc = 0; kc < 4; kc++) {
            uint32_t af[2][4], bf[8][2];
#pragma unroll
            for (int mt = 0; mt < 2; mt++) {
                int am = (mw + mt * 16 + g) * ASTR2 + kc * 8 + q4;
                af[mt][0] = As[am];
                af[mt][1] = As[am + 8 * ASTR2];
                af[mt][2] = As[am + 4];
                af[mt][3] = As[am + 8 * ASTR2 + 4];
            }
#pragma unroll
            for (int jt = 0; jt < 8; jt++) {
                uint2 b = *(const uint2*)(Bs + (nw + jt * 8 + g) * BSTR2 + kc * 8 + q4 * 2);
                bf[jt][0] = b.x; bf[jt][1] = b.y;
            }
#pragma unroll
            for (int mt = 0; mt < 2; mt++)
#pragma unroll
                for (int jt = 0; jt < 8; jt++)
                    mma_f16(c[mt][jt], af[mt], bf[jt][0], bf[jt][1]);
        }
    }

    const int mode = (flags & 1) ? (m0 >> 9) : 3;   // 0=Q 1=K 2=V 3=out
    if (mode == 1) {
        __nv_bfloat16* kb2 = (__nv_bfloat16*)g_k2;
#pragma unroll
        for (int mt = 0; mt < 2; mt++) {
#pragma unroll
            for (int jt = 0; jt < 8; jt++) {
                int ch = m0 - 512 + mw + mt * 16 + g;
                int h2 = ch >> 6, d = ch & 63;
                int j = n0 + nw + jt * 8 + q4 * 2;
                int base0 = (h2 * 4096 + j) * 64;
                kb2[base0 + kpos(d)]          = __float2bfloat16(c[mt][jt][0]);
                kb2[base0 + 64 + kpos(d)]     = __float2bfloat16(c[mt][jt][1]);
                kb2[base0 + kpos(d + 8)]      = __float2bfloat16(c[mt][jt][2]);
                kb2[base0 + 64 + kpos(d + 8)] = __float2bfloat16(c[mt][jt][3]);
            }
        }
        return;
    }
    if (mode == 2) {
        // V -> g_v3 smem-image layout: word = d*40 + f(jp), tile = j>>6
#pragma unroll
        for (int mt = 0; mt < 2; mt++) {
#pragma unroll
            for (int jt = 0; jt < 8; jt++) {
                int ch = m0 - 1024 + mw + mt * 16 + g;
                int h2 = ch >> 6, d = ch & 63;
                int j = n0 + nw + jt * 8 + q4 * 2;
                int tile = j >> 6, jp = (j & 63) >> 1;
                int f = (jp >> 3) * 8 + (jp & 3) * 2 + ((jp >> 2) & 1);
                uint32_t* vb = g_v3 + (h2 * 64 + tile) * 2560;
                vb[d * 40 + f]       = pack_f16x2(c[mt][jt][0], c[mt][jt][1]);
                vb[(d + 8) * 40 + f] = pack_f16x2(c[mt][jt][2], c[mt][jt][3]);
            }
        }
        return;
    }
    if (mode == 0) {
        const float sc = 0.18033688011112042f;   // hd^-0.5 * log2(e)
        float* C = g_qkv;
#pragma unroll
        for (int mt = 0; mt < 2; mt++) {
#pragma unroll
            for (int jt = 0; jt < 8; jt++) {
                int row = m0 + mw + mt * 16 + g;
                int col = n0 + nw + jt * 8 + q4 * 2;
                *(float2*)&C[row * NTOK + col] =
                    make_float2(c[mt][jt][0] * sc, c[mt][jt][1] * sc);
                *(float2*)&C[(row + 8) * NTOK + col] =
                    make_float2(c[mt][jt][2] * sc, c[mt][jt][3] * sc);
            }
        }
        return;
    }
#pragma unroll
    for (int mt = 0; mt < 2; mt++) {
#pragma unroll
        for (int jt = 0; jt < 8; jt++) {
            int row = m0 + mw + mt * 16 + g;
            int col = n0 + nw + jt * 8 + q4 * 2;
            float b0v = bias[row], b1v = bias[row + 8];
            float2 r0 = *(const float2*)&res[row * NTOK + col];
            float2 r1 = *(const float2*)&res[(row + 8) * NTOK + col];
            *(float2*)&Cg[row * NTOK + col] =
                make_float2(c[mt][jt][0] + b0v + r0.x, c[mt][jt][1] + b0v + r0.y);
            *(float2*)&Cg[(row + 8) * NTOK + col] =
                make_float2(c[mt][jt][2] + b1v + r1.x, c[mt][jt][3] + b1v + r1.y);
        }
    }
}

// ---------------------------------------------------------------------------
// Flash attention: 3-stage cp.async ring for K/V (barrier gates data staged
// 2 iters earlier). Compute code byte-identical to round 16 (bf16 S, packed
// ex2 softmax, ones-mma l, fp16 PV).
// Smem: K ring 3x10240 + V ring 3x10240 = 61440 B.
// ---------------------------------------------------------------------------
__global__ __launch_bounds__(256, 2) void flash_attn() {
    extern __shared__ char sm[];
    uint32_t* Kb = (uint32_t*)sm;                  // [3][2560]
    uint32_t* Vb = (uint32_t*)(sm + 30720);        // [3][2560]
    const uint32_t sbK = smem_u32(sm);
    const uint32_t sbV = sbK + 30720;

    const int t = threadIdx.x;
    const int w = t >> 5;
    const int lane = t & 31;
    const int g = lane >> 2;
    const int q4 = lane & 3;
    const int i0 = blockIdx.x * 128;
    const int h  = blockIdx.y;

    // ---- Q fragments (bf16 A-frags, proven)
    uint32_t Qa[4][4];
    {
        const float* qb = g_qkv + (h * HD) * NTOK + i0 + w * 16 + g;
#pragma unroll
        for (int kc = 0; kc < 4; kc++) {
            int d0 = kc * 16 + q4 * 2;
            Qa[kc][0] = pack_bf16x2(qb[d0 * NTOK],           qb[(d0 + 1) * NTOK]);
            Qa[kc][1] = pack_bf16x2(qb[d0 * NTOK + 8],       qb[(d0 + 1) * NTOK + 8]);
            Qa[kc][2] = pack_bf16x2(qb[(d0 + 8) * NTOK],     qb[(d0 + 9) * NTOK]);
            Qa[kc][3] = pack_bf16x2(qb[(d0 + 8) * NTOK + 8], qb[(d0 + 9) * NTOK + 8]);
        }
    }

    // staging sources
    const uint32_t* srcK = g_k2 + (h * 4096) * 32;       // + tile*2048
    const uint32_t* srcV = g_v3 + (h * 64) * 2560;       // + tile*2560

    // K: 512 chunks/tile, thread does 2; V: 640 chunks/tile, thread does 2-3
    const int kc0 = t * 2;
#define STAGE(tile, slot) do {                                                  \
    const uint32_t* ksrc = srcK + (tile) * 2048;                                \
    const uint32_t* vsrc = srcV + (tile) * 2560;                                \
    const uint32_t kd = sbK + (slot) * 10240;                                   \
    const uint32_t vd = sbV + (slot) * 10240;                                   \
    cp16(kd + (((kc0)     >> 3) * 40 + ((kc0)     & 7) * 4) * 4,                \
         ksrc + ((kc0)     >> 3) * 32 + ((kc0)     & 7) * 4);                   \
    cp16(kd + (((kc0 + 1) >> 3) * 40 + ((kc0 + 1) & 7) * 4) * 4,                \
         ksrc + ((kc0 + 1) >> 3) * 32 + ((kc0 + 1) & 7) * 4);                   \
    cp16(vd + t * 16,         vsrc + t * 4);                                    \
    cp16(vd + (t + 256) * 16, vsrc + (t + 256) * 4);                            \
    if (t < 128) cp16(vd + (t + 512) * 16, vsrc + (t + 512) * 4);               \
    asm volatile("cp.async.commit_group;" ::: "memory");                        \
} while (0)

    // prologue: tiles 0, 1 into slots 0, 1
    STAGE(0, 0);
    STAGE(1, 1);

    float O[8][4] = {};
    float lacc[4] = {};
    const uint32_t ones = (g == 0) ? 0x3C003C00u : 0u;

    int slot = 0;
    for (int kt = 0; kt < 64; kt++) {
        if (kt < 62)
            asm volatile("cp.async.wait_group 1;" ::: "memory");
        else
            asm volatile("cp.async.wait_group 0;" ::: "memory");
        __syncthreads();   // data(kt) visible; all warps done with slot (kt-1)%3

        if (kt < 62) {
            int ns = slot + 2; if (ns >= 3) ns -= 3;
            STAGE(kt + 2, ns);
        }

        // ---- S = Q K^T (bf16 m16n8k16, proven)
        const uint32_t* Kc = Kb + slot * 2560;
        float S[8][4] = {};
#pragma unroll
        for (int kc = 0; kc < 4; kc++) {
#pragma unroll
            for (int jt = 0; jt < 8; jt++) {
                uint2 b = *(const uint2*)(Kc + (jt * 8 + g) * 40 + kc * 8 + q4 * 2);
                mma_bf16(S[jt], Qa[kc], b.x, b.y);
            }
        }

        // ---- softmax (packed ex2) + PV + ones-mma l (proven)
        const uint32_t* Vc = Vb + slot * 2560;
#pragma unroll
        for (int kc2 = 0; kc2 < 4; kc2++) {
            uint32_t Pa[4];
            Pa[0] = ex2_f16x2(pack_f16x2(S[2 * kc2][0],     S[2 * kc2][1]));
            Pa[1] = ex2_f16x2(pack_f16x2(S[2 * kc2][2],     S[2 * kc2][3]));
            Pa[2] = ex2_f16x2(pack_f16x2(S[2 * kc2 + 1][0], S[2 * kc2 + 1][1]));
            Pa[3] = ex2_f16x2(pack_f16x2(S[2 * kc2 + 1][2], S[2 * kc2 + 1][3]));
            mma_f16(lacc, Pa, ones, ones);
#pragma unroll
            for (int nt = 0; nt < 8; nt++) {
                uint2 bv = *(const uint2*)(Vc + (nt * 8 + g) * 40 + kc2 * 8 + q4 * 2);
                mma_f16(O[nt], Pa, bv.x, bv.y);
            }
        }

        slot++; if (slot == 3) slot = 0;
    }

    float l0 = __shfl_sync(0xffffffffu, lacc[0], lane & ~3);
    float l1 = __shfl_sync(0xffffffffu, lacc[2], lane & ~3);

    float inv0 = 1.0f / l0, inv1 = 1.0f / l1;
    const int tok = i0 + w * 16 + g;
    uint32_t* at0 = g_att_t + tok * 256;
    uint32_t* at1 = at0 + 8 * 256;
#pragma unroll
    for (int nt = 0; nt < 8; nt++) {
        int kc = h * 4 + (nt >> 1);
        int p = (nt * 4 + q4) & 7;
        int wrd = kc * 8 + (p & 3) * 2 + (p >> 2);
        at0[wrd] = pack_f16x2(O[nt][0] * inv0, O[nt][1] * inv0);
        at1[wrd] = pack_f16x2(O[nt][2] * inv1, O[nt][3] * inv1);
    }
}

extern "C" void kernel_launch(void* const* d_in, const int* in_sizes, int n_in,
                              void* d_out, int out_size) {
    const float* x     = (const float*)d_in[0];
    const float* w_qkv = (const float*)d_in[1];
    const float* w_out = (const float*)d_in[2];
    const float* b_out = (const float*)d_in[3];
    float* out = (float*)d_out;

    cudaFuncSetAttribute(flash_attn, cudaFuncAttributeMaxDynamicSharedMemorySize, 61440);
    cudaFuncSetAttribute(gemm_f16, cudaFuncAttributeMaxDynamicSharedMemorySize, 77824);

    conv_w<<<2048, 256>>>(w_qkv, w_out);
    trans_x<<<dim3(64, 8), 256>>>(x);
    gemm_f16<<<dim3(32, 12), 256, 77824>>>(nullptr, nullptr, nullptr, /*flags=*/1);
    flash_attn<<<dim3(32, 8), 256, 61440>>>();
    gemm_f16<<<dim3(32, 4), 256, 77824>>>(out, b_out, x, /*flags=*/0);
}